// round 5
// baseline (speedup 1.0000x reference)
#include <cuda_runtime.h>
#include <cuda_bf16.h>
#include <cstdint>
#include <math.h>

#define E_   30
#define NB_  12
#define F_   1024
#define H_   32
#define B_   8192
#define L_   128
#define EPS_ 1e-12f

#define EPC  5            // emotions per CTA
#define NEG  6            // emotion groups (EPC*NEG = E)
#define ROWS 256          // B rows per CTA
#define KC   32           // k per chunk
#define NCH  (F_ / KC)    // 32 chunks

__device__ float g_w[E_ * B_ * NB_];

// ---------------- smem layout (bytes) ----------------
// constants
#define OFF_BW   0                       // 5*12 f
#define OFF_B2   256                     // 5*12 f
#define OFF_B1   512                     // 5*32 f
#define OFF_W2   1152                    // 5*384 f = 7680B
#define OFF_X    8832                    // 2 bufs x (hi 20480 + lo 20480)
#define XHI(p)   (OFF_X + (p) * 40960)
#define XLO(p)   (XHI(p) + 20480)
#define OFF_WB   (OFF_X + 81920)         // 2 bufs x (hi 12800 + lo 12800)
#define WHI(p)   (OFF_WB + (p) * 25600)
#define WLO(p)   (WHI(p) + 12800)
#define SMEM_BYTES (OFF_WB + 51200)      // 141952

__device__ __forceinline__ uint32_t smem_u32(const void* p) {
    uint32_t a;
    asm("{ .reg .u64 t; cvta.to.shared.u64 t, %1; cvt.u32.u64 %0, t; }"
        : "=r"(a) : "l"(p));
    return a;
}
__device__ __forceinline__ void ldmx4(uint32_t* r, uint32_t a) {
    asm volatile("ldmatrix.sync.aligned.m8n8.x4.shared.b16 {%0,%1,%2,%3}, [%4];"
        : "=r"(r[0]), "=r"(r[1]), "=r"(r[2]), "=r"(r[3]) : "r"(a));
}
__device__ __forceinline__ void ldmx4t(uint32_t* r, uint32_t a) {
    asm volatile("ldmatrix.sync.aligned.m8n8.x4.trans.shared.b16 {%0,%1,%2,%3}, [%4];"
        : "=r"(r[0]), "=r"(r[1]), "=r"(r[2]), "=r"(r[3]) : "r"(a));
}
__device__ __forceinline__ void mma_bf16(float* c, const uint32_t* a, const uint32_t* b) {
    asm volatile(
        "mma.sync.aligned.m16n8k16.row.col.f32.bf16.bf16.f32 "
        "{%0,%1,%2,%3}, {%4,%5,%6,%7}, {%8,%9}, {%0,%1,%2,%3};"
        : "+f"(c[0]), "+f"(c[1]), "+f"(c[2]), "+f"(c[3])
        : "r"(a[0]), "r"(a[1]), "r"(a[2]), "r"(a[3]), "r"(b[0]), "r"(b[1]));
}
// split fp32 into hi/lo bf16; pack pairs into b32 (low half = even index)
__device__ __forceinline__ void split2(float x, float y, uint32_t& hi, uint32_t& lo) {
    __nv_bfloat16 hx = __float2bfloat16(x);
    __nv_bfloat16 hy = __float2bfloat16(y);
    __nv_bfloat16 lx = __float2bfloat16(x - __bfloat162float(hx));
    __nv_bfloat16 ly = __float2bfloat16(y - __bfloat162float(hy));
    hi = (uint32_t)__bfloat16_as_ushort(hx) | ((uint32_t)__bfloat16_as_ushort(hy) << 16);
    lo = (uint32_t)__bfloat16_as_ushort(lx) | ((uint32_t)__bfloat16_as_ushort(ly) << 16);
}
__device__ __forceinline__ float selu(float v) {
    const float S  = 1.0507009873554805f;
    const float SA = 1.0507009873554805f * 1.6732632423543772f;
    return (v > 0.f) ? S * v : SA * (__expf(v) - 1.f);
}

// ---------------------------------------------------------------------------
// Kernel A: bf16x3 split GEMM (X@W1 per emotion) via mma.sync + fused layer2
// grid (32, 6), 256 threads
// ---------------------------------------------------------------------------
__global__ void __launch_bounds__(256, 1) mlp_tc_kernel(
    const float* __restrict__ X,    // (B,F)
    const float* __restrict__ bw,   // (E,NB)
    const float* __restrict__ W1,   // (E,F,H)
    const float* __restrict__ b1,   // (E,H)
    const float* __restrict__ W2,   // (E,H,NB)
    const float* __restrict__ b2)   // (E,NB)
{
    extern __shared__ char smem[];
    const uint32_t sb = smem_u32(smem);
    const int tid  = threadIdx.x;
    const int w    = tid >> 5;
    const int lane = tid & 31;
    const int b0   = blockIdx.x * ROWS;
    const int e0   = blockIdx.y * EPC;

    // stage epilogue constants
    for (int t = tid; t < EPC * NB_; t += 256) {
        ((float*)(smem + OFF_BW))[t] = bw[e0 * NB_ + t];
        ((float*)(smem + OFF_B2))[t] = b2[e0 * NB_ + t];
    }
    for (int t = tid; t < EPC * H_; t += 256)
        ((float*)(smem + OFF_B1))[t] = b1[e0 * H_ + t];
    for (int t = tid; t < EPC * H_ * NB_; t += 256)
        ((float*)(smem + OFF_W2))[t] = W2[(size_t)e0 * H_ * NB_ + t];

    float acc[EPC][8][4];
    #pragma unroll
    for (int e = 0; e < EPC; e++)
        #pragma unroll
        for (int i = 0; i < 8; i++)
            #pragma unroll
            for (int j = 0; j < 4; j++) acc[e][i][j] = 0.f;

    // ---- staging helpers (inlined via lambdas) ----
    auto stsX = [&](const float4* xv, int p) {
        #pragma unroll
        for (int it = 0; it < 8; it++) {
            int g = it * 256 + tid;
            int row = g >> 3, q = g & 7;
            uint32_t h01, l01, h23, l23;
            split2(xv[it].x, xv[it].y, h01, l01);
            split2(xv[it].z, xv[it].w, h23, l23);
            *reinterpret_cast<uint2*>(smem + XHI(p) + row * 80 + q * 8) =
                make_uint2(h01, h23);
            *reinterpret_cast<uint2*>(smem + XLO(p) + row * 80 + q * 8) =
                make_uint2(l01, l23);
        }
    };
    auto ldgX = [&](float4* xv, int c) {
        const int k0 = c * KC;
        #pragma unroll
        for (int it = 0; it < 8; it++) {
            int g = it * 256 + tid;
            int row = g >> 3, q = g & 7;
            xv[it] = *reinterpret_cast<const float4*>(
                &X[(size_t)(b0 + row) * F_ + k0 + q * 4]);
        }
    };
    auto stageW = [&](int c, int p) {
        const int k0 = c * KC;
        #pragma unroll
        for (int it = 0; it < 5; it++) {
            int g = it * 256 + tid;
            int e = g >> 8, r = g & 255;
            int kr = r >> 3, q = r & 7;
            float4 v = *reinterpret_cast<const float4*>(
                &W1[((size_t)(e0 + e) * F_ + k0 + kr) * H_ + q * 4]);
            uint32_t h01, l01, h23, l23;
            split2(v.x, v.y, h01, l01);
            split2(v.z, v.w, h23, l23);
            *reinterpret_cast<uint2*>(smem + WHI(p) + e * 2560 + kr * 80 + q * 8) =
                make_uint2(h01, h23);
            *reinterpret_cast<uint2*>(smem + WLO(p) + e * 2560 + kr * 80 + q * 8) =
                make_uint2(l01, l23);
        }
    };

    // prologue: stage chunk 0
    {
        float4 xv[8];
        ldgX(xv, 0);
        stsX(xv, 0);
        stageW(0, 0);
    }
    __syncthreads();

    const int lr16 = lane & 15;
    const int lq16 = (lane >> 4) * 16;   // byte offset for upper half of x4

    for (int c = 0; c < NCH; c++) {
        const int p = c & 1;

        float4 xv[8];
        if (c + 1 < NCH) ldgX(xv, c + 1);   // prefetch next X (hidden by MMAs)

        // ---- MMA on buffer p ----
        #pragma unroll
        for (int ks = 0; ks < 2; ks++) {
            uint32_t Ah[2][4], Al[2][4];
            #pragma unroll
            for (int mt = 0; mt < 2; mt++) {
                uint32_t ar = (uint32_t)((w * 32 + mt * 16 + lr16) * 80 + ks * 32 + lq16);
                ldmx4(Ah[mt], sb + XHI(p) + ar);
                ldmx4(Al[mt], sb + XLO(p) + ar);
            }
            #pragma unroll
            for (int e = 0; e < EPC; e++) {
                uint32_t br = (uint32_t)(e * 2560 + (ks * 16 + lr16) * 80 + lq16);
                #pragma unroll
                for (int np = 0; np < 2; np++) {
                    uint32_t Bh[4], Bl[4];
                    ldmx4t(Bh, sb + WHI(p) + br + np * 32);
                    ldmx4t(Bl, sb + WLO(p) + br + np * 32);
                    #pragma unroll
                    for (int mt = 0; mt < 2; mt++) {
                        #pragma unroll
                        for (int t = 0; t < 2; t++) {
                            float* C = acc[e][mt * 4 + np * 2 + t];
                            mma_bf16(C, Ah[mt], &Bh[t * 2]);
                            mma_bf16(C, Al[mt], &Bh[t * 2]);
                            mma_bf16(C, Ah[mt], &Bl[t * 2]);
                        }
                    }
                }
            }
        }

        if (c + 1 < NCH) {
            stsX(xv, (c + 1) & 1);
            stageW(c + 1, (c + 1) & 1);
        }
        __syncthreads();
    }

    // -------- epilogue: selu + layer2 + signed-L1 normalize --------
    float* Hs = (float*)(smem + OFF_X);          // [256][33], aliases X bufs
    const float* b1s = (const float*)(smem + OFF_B1);
    const float* b2s = (const float*)(smem + OFF_B2);
    const float* bws = (const float*)(smem + OFF_BW);
    const float* W2s = (const float*)(smem + OFF_W2);

    for (int e = 0; e < EPC; e++) {
        #pragma unroll
        for (int mt = 0; mt < 2; mt++) {
            int r0 = w * 32 + mt * 16 + (lane >> 2);
            #pragma unroll
            for (int nt = 0; nt < 4; nt++) {
                int col = nt * 8 + (lane & 3) * 2;
                float ba = b1s[e * H_ + col], bb = b1s[e * H_ + col + 1];
                const float* C = acc[e][mt * 4 + nt];
                Hs[r0 * 33 + col]           = selu(C[0] + ba);
                Hs[r0 * 33 + col + 1]       = selu(C[1] + bb);
                Hs[(r0 + 8) * 33 + col]     = selu(C[2] + ba);
                Hs[(r0 + 8) * 33 + col + 1] = selu(C[3] + bb);
            }
        }
        __syncthreads();

        {
            float h[H_];
            #pragma unroll
            for (int hh = 0; hh < H_; hh++) h[hh] = Hs[tid * 33 + hh];

            float ew[NB_]; float s = 0.f;
            #pragma unroll
            for (int n = 0; n < NB_; n++) { ew[n] = __expf(bws[e * NB_ + n]); s += ew[n]; }
            const float inv_s = 1.f / fmaxf(s, EPS_);

            float upd[NB_]; float sa = 0.f;
            #pragma unroll
            for (int n = 0; n < NB_; n++) {
                float a2 = b2s[e * NB_ + n];
                #pragma unroll
                for (int hh = 0; hh < H_; hh++)
                    a2 = fmaf(h[hh], W2s[e * H_ * NB_ + hh * NB_ + n], a2);
                float u = fmaf(ew[n], inv_s, a2);
                upd[n] = u;
                sa += fabsf(u);
            }
            const float inv = 1.f / fmaxf(sa, EPS_);

            float4* dst = reinterpret_cast<float4*>(
                &g_w[((size_t)(e0 + e) * B_ + b0 + tid) * NB_]);
            dst[0] = make_float4(upd[0] * inv, upd[1] * inv, upd[2]  * inv, upd[3]  * inv);
            dst[1] = make_float4(upd[4] * inv, upd[5] * inv, upd[6]  * inv, upd[7]  * inv);
            dst[2] = make_float4(upd[8] * inv, upd[9] * inv, upd[10] * inv, upd[11] * inv);
        }
        __syncthreads();
    }
}

// ---------------------------------------------------------------------------
// Kernel B: mixed = w @ D, softmax over L (no max needed: |mixed| < 1).
// One warp per b, lane holds 4 l's. grid (B/8), 256 threads.
// ---------------------------------------------------------------------------
__global__ __launch_bounds__(256) void mix_softmax_kernel(
    const float* __restrict__ D,   // (B, NB, L)
    float* __restrict__ out)       // (E, B, L)
{
    const int warp = threadIdx.x >> 5;
    const int lane = threadIdx.x & 31;
    const size_t b = (size_t)blockIdx.x * 8 + warp;

    float4 Dreg[NB_];
    #pragma unroll
    for (int n = 0; n < NB_; n++)
        Dreg[n] = *reinterpret_cast<const float4*>(
            &D[(b * NB_ + n) * L_ + lane * 4]);

    for (int e = 0; e < E_; e++) {
        float wv = (lane < NB_) ? g_w[((size_t)e * B_ + b) * NB_ + lane] : 0.f;

        float4 v = make_float4(0.f, 0.f, 0.f, 0.f);
        #pragma unroll
        for (int n = 0; n < NB_; n++) {
            float wn = __shfl_sync(0xffffffffu, wv, n);
            v.x = fmaf(wn, Dreg[n].x, v.x);
            v.y = fmaf(wn, Dreg[n].y, v.y);
            v.z = fmaf(wn, Dreg[n].z, v.z);
            v.w = fmaf(wn, Dreg[n].w, v.w);
        }

        float e0 = __expf(v.x), e1 = __expf(v.y);
        float e2 = __expf(v.z), e3 = __expf(v.w);
        float sm = (e0 + e1) + (e2 + e3);
        #pragma unroll
        for (int off = 16; off > 0; off >>= 1)
            sm += __shfl_xor_sync(0xffffffffu, sm, off);

        const float inv = 1.f / sm;
        *reinterpret_cast<float4*>(&out[((size_t)e * B_ + b) * L_ + lane * 4]) =
            make_float4(e0 * inv, e1 * inv, e2 * inv, e3 * inv);
    }
}

// ---------------------------------------------------------------------------
extern "C" void kernel_launch(void* const* d_in, const int* in_sizes, int n_in,
                              void* d_out, int out_size)
{
    const float* D  = (const float*)d_in[0];  // (B,NB,L)
    const float* X  = (const float*)d_in[1];  // (B,F)
    const float* bw = (const float*)d_in[2];  // (E,1,NB,1)
    const float* W1 = (const float*)d_in[3];  // (E,F,H)
    const float* b1 = (const float*)d_in[4];  // (E,H)
    const float* W2 = (const float*)d_in[5];  // (E,H,NB)
    const float* b2 = (const float*)d_in[6];  // (E,NB)
    float* out = (float*)d_out;               // (E,B,L)

    static int smem_set = 0;
    if (!smem_set) {
        cudaFuncSetAttribute(mlp_tc_kernel,
                             cudaFuncAttributeMaxDynamicSharedMemorySize, SMEM_BYTES);
        smem_set = 1;
    }
    dim3 gA(B_ / ROWS, NEG);
    mlp_tc_kernel<<<gA, 256, SMEM_BYTES>>>(X, bw, W1, b1, W2, b2);
    mix_softmax_kernel<<<B_ / 8, 256>>>(D, out);
}

// round 9
// speedup vs baseline: 1.4543x; 1.4543x over previous
#include <cuda_runtime.h>
#include <cuda_bf16.h>
#include <cstdint>
#include <math.h>

#define E_   30
#define NB_  12
#define F_   1024
#define H_   32
#define B_   8192
#define L_   128
#define EPS_ 1e-12f

#define EPC  3            // emotions per CTA
#define NEG  10           // emotion groups (EPC*NEG = E)
#define ROWS 128          // B rows per CTA
#define KC   32           // k per chunk
#define NCH  (F_ / KC)    // 32 chunks

__device__ float g_w[E_ * B_ * NB_];

// ---------------- smem layout (bytes) ----------------
#define OFF_BW   0                       // 3*12 f
#define OFF_B2   256                     // 3*12 f
#define OFF_B1   512                     // 3*32 f
#define OFF_W2   1024                    // 3*384 f = 4608B
#define OFF_X    5888                    // 2 bufs x (hi 10240 + lo 10240)
#define XHI(p)   (OFF_X + (p) * 20480)
#define XLO(p)   (XHI(p) + 10240)
#define OFF_WB   (OFF_X + 40960)         // 2 bufs x (hi 7680 + lo 7680)
#define WHI(p)   (OFF_WB + (p) * 15360)
#define WLO(p)   (WHI(p) + 7680)
#define SMEM_BYTES (OFF_WB + 30720)      // 77568  -> 2 CTAs/SM

__device__ __forceinline__ uint32_t smem_u32(const void* p) {
    uint32_t a;
    asm("{ .reg .u64 t; cvta.to.shared.u64 t, %1; cvt.u32.u64 %0, t; }"
        : "=r"(a) : "l"(p));
    return a;
}
__device__ __forceinline__ void ldmx4(uint32_t* r, uint32_t a) {
    asm volatile("ldmatrix.sync.aligned.m8n8.x4.shared.b16 {%0,%1,%2,%3}, [%4];"
        : "=r"(r[0]), "=r"(r[1]), "=r"(r[2]), "=r"(r[3]) : "r"(a));
}
__device__ __forceinline__ void ldmx4t(uint32_t* r, uint32_t a) {
    asm volatile("ldmatrix.sync.aligned.m8n8.x4.trans.shared.b16 {%0,%1,%2,%3}, [%4];"
        : "=r"(r[0]), "=r"(r[1]), "=r"(r[2]), "=r"(r[3]) : "r"(a));
}
__device__ __forceinline__ void mma_bf16(float* c, const uint32_t* a, const uint32_t* b) {
    asm volatile(
        "mma.sync.aligned.m16n8k16.row.col.f32.bf16.bf16.f32 "
        "{%0,%1,%2,%3}, {%4,%5,%6,%7}, {%8,%9}, {%0,%1,%2,%3};"
        : "+f"(c[0]), "+f"(c[1]), "+f"(c[2]), "+f"(c[3])
        : "r"(a[0]), "r"(a[1]), "r"(a[2]), "r"(a[3]), "r"(b[0]), "r"(b[1]));
}
__device__ __forceinline__ void split2(float x, float y, uint32_t& hi, uint32_t& lo) {
    __nv_bfloat16 hx = __float2bfloat16(x);
    __nv_bfloat16 hy = __float2bfloat16(y);
    __nv_bfloat16 lx = __float2bfloat16(x - __bfloat162float(hx));
    __nv_bfloat16 ly = __float2bfloat16(y - __bfloat162float(hy));
    hi = (uint32_t)__bfloat16_as_ushort(hx) | ((uint32_t)__bfloat16_as_ushort(hy) << 16);
    lo = (uint32_t)__bfloat16_as_ushort(lx) | ((uint32_t)__bfloat16_as_ushort(ly) << 16);
}
__device__ __forceinline__ float selu(float v) {
    const float S  = 1.0507009873554805f;
    const float SA = 1.0507009873554805f * 1.6732632423543772f;
    return (v > 0.f) ? S * v : SA * (__expf(v) - 1.f);
}

// ---------------------------------------------------------------------------
// Kernel A: bf16x3 split GEMM (X@W1 per emotion) via mma.sync + fused layer2
// grid (64, 10), 256 threads, 2 CTAs/SM
// ---------------------------------------------------------------------------
__global__ void __launch_bounds__(256, 2) mlp_tc_kernel(
    const float* __restrict__ X,    // (B,F)
    const float* __restrict__ bw,   // (E,NB)
    const float* __restrict__ W1,   // (E,F,H)
    const float* __restrict__ b1,   // (E,H)
    const float* __restrict__ W2,   // (E,H,NB)
    const float* __restrict__ b2)   // (E,NB)
{
    extern __shared__ char smem[];
    const uint32_t sb = smem_u32(smem);
    const int tid  = threadIdx.x;
    const int w    = tid >> 5;
    const int lane = tid & 31;
    const int b0   = blockIdx.x * ROWS;
    const int e0   = blockIdx.y * EPC;

    for (int t = tid; t < EPC * NB_; t += 256) {
        ((float*)(smem + OFF_BW))[t] = bw[e0 * NB_ + t];
        ((float*)(smem + OFF_B2))[t] = b2[e0 * NB_ + t];
    }
    for (int t = tid; t < EPC * H_; t += 256)
        ((float*)(smem + OFF_B1))[t] = b1[e0 * H_ + t];
    for (int t = tid; t < EPC * H_ * NB_; t += 256)
        ((float*)(smem + OFF_W2))[t] = W2[(size_t)e0 * H_ * NB_ + t];

    float acc[EPC][4][4];
    #pragma unroll
    for (int e = 0; e < EPC; e++)
        #pragma unroll
        for (int i = 0; i < 4; i++)
            #pragma unroll
            for (int j = 0; j < 4; j++) acc[e][i][j] = 0.f;

    // X: 128 rows x 8 qgroups = 1024 tasks / 256 thr = 4
    const int xrow = tid >> 3, xq = tid & 7;            // +32 rows per it
    // W: 3e x 32 rows x 8 q = 768 tasks / 256 thr = 3
    auto ldgX = [&](float4* xv, int c) {
        const int k0 = c * KC;
        #pragma unroll
        for (int it = 0; it < 4; it++)
            xv[it] = *reinterpret_cast<const float4*>(
                &X[(size_t)(b0 + it * 32 + xrow) * F_ + k0 + xq * 4]);
    };
    auto stsX = [&](const float4* xv, int p) {
        #pragma unroll
        for (int it = 0; it < 4; it++) {
            uint32_t h01, l01, h23, l23;
            split2(xv[it].x, xv[it].y, h01, l01);
            split2(xv[it].z, xv[it].w, h23, l23);
            int off = (it * 32 + xrow) * 80 + xq * 8;
            *reinterpret_cast<uint2*>(smem + XHI(p) + off) = make_uint2(h01, h23);
            *reinterpret_cast<uint2*>(smem + XLO(p) + off) = make_uint2(l01, l23);
        }
    };
    auto ldgW = [&](float4* wv, int c) {
        const int k0 = c * KC;
        #pragma unroll
        for (int it = 0; it < 3; it++) {
            int g = it * 256 + tid;
            int e = g >> 8, r = g & 255;
            int kr = r >> 3, q = r & 7;
            wv[it] = *reinterpret_cast<const float4*>(
                &W1[((size_t)(e0 + e) * F_ + k0 + kr) * H_ + q * 4]);
        }
    };
    auto stsW = [&](const float4* wv, int p) {
        #pragma unroll
        for (int it = 0; it < 3; it++) {
            int g = it * 256 + tid;
            int e = g >> 8, r = g & 255;
            int kr = r >> 3, q = r & 7;
            uint32_t h01, l01, h23, l23;
            split2(wv[it].x, wv[it].y, h01, l01);
            split2(wv[it].z, wv[it].w, h23, l23);
            int off = e * 2560 + kr * 80 + q * 8;
            *reinterpret_cast<uint2*>(smem + WHI(p) + off) = make_uint2(h01, h23);
            *reinterpret_cast<uint2*>(smem + WLO(p) + off) = make_uint2(l01, l23);
        }
    };

    {
        float4 xv[4], wv[3];
        ldgX(xv, 0); ldgW(wv, 0);
        stsX(xv, 0); stsW(wv, 0);
    }
    __syncthreads();

    const int lr16 = lane & 15;
    const int lq16 = (lane >> 4) * 16;

    for (int c = 0; c < NCH; c++) {
        const int p = c & 1;

        float4 xv[4], wv[3];
        if (c + 1 < NCH) { ldgX(xv, c + 1); ldgW(wv, c + 1); }

        #pragma unroll
        for (int ks = 0; ks < 2; ks++) {
            uint32_t Ah[4], Al[4];
            uint32_t ar = sb + XHI(p) + (uint32_t)((w * 16 + lr16) * 80 + ks * 32 + lq16);
            ldmx4(Ah, ar);
            ldmx4(Al, ar + 10240);
            #pragma unroll
            for (int e = 0; e < EPC; e++) {
                uint32_t br = sb + WHI(p) +
                    (uint32_t)(e * 2560 + (ks * 16 + lr16) * 80 + lq16);
                #pragma unroll
                for (int np = 0; np < 2; np++) {
                    uint32_t Bh[4], Bl[4];
                    ldmx4t(Bh, br + np * 32);
                    ldmx4t(Bl, br + np * 32 + 7680);
                    #pragma unroll
                    for (int t = 0; t < 2; t++) {
                        float* C = acc[e][np * 2 + t];
                        mma_bf16(C, Ah, &Bh[t * 2]);
                        mma_bf16(C, Al, &Bh[t * 2]);
                        mma_bf16(C, Ah, &Bl[t * 2]);
                    }
                }
            }
        }

        if (c + 1 < NCH) { stsX(xv, p ^ 1); stsW(wv, p ^ 1); }
        __syncthreads();
    }

    // -------- epilogue --------
    float* Hs = (float*)(smem + OFF_X);          // [128][33]
    const float* b1s = (const float*)(smem + OFF_B1);
    const float* b2s = (const float*)(smem + OFF_B2);
    const float* bws = (const float*)(smem + OFF_BW);
    const float* W2s = (const float*)(smem + OFF_W2);

    for (int e = 0; e < EPC; e++) {
        const int r0 = w * 16 + (lane >> 2);
        #pragma unroll
        for (int nt = 0; nt < 4; nt++) {
            int col = nt * 8 + (lane & 3) * 2;
            float ba = b1s[e * H_ + col], bb = b1s[e * H_ + col + 1];
            const float* C = acc[e][nt];
            Hs[r0 * 33 + col]           = selu(C[0] + ba);
            Hs[r0 * 33 + col + 1]       = selu(C[1] + bb);
            Hs[(r0 + 8) * 33 + col]     = selu(C[2] + ba);
            Hs[(r0 + 8) * 33 + col + 1] = selu(C[3] + bb);
        }
        __syncthreads();

        if (tid < ROWS) {
            float h[H_];
            #pragma unroll
            for (int hh = 0; hh < H_; hh++) h[hh] = Hs[tid * 33 + hh];

            float ew[NB_]; float s = 0.f;
            #pragma unroll
            for (int n = 0; n < NB_; n++) { ew[n] = __expf(bws[e * NB_ + n]); s += ew[n]; }
            const float inv_s = 1.f / fmaxf(s, EPS_);

            float upd[NB_]; float sa = 0.f;
            #pragma unroll
            for (int n = 0; n < NB_; n++) {
                float a2 = b2s[e * NB_ + n];
                #pragma unroll
                for (int hh = 0; hh < H_; hh++)
                    a2 = fmaf(h[hh], W2s[e * H_ * NB_ + hh * NB_ + n], a2);
                float u = fmaf(ew[n], inv_s, a2);
                upd[n] = u;
                sa += fabsf(u);
            }
            const float inv = 1.f / fmaxf(sa, EPS_);

            float4* dst = reinterpret_cast<float4*>(
                &g_w[((size_t)(e0 + e) * B_ + b0 + tid) * NB_]);
            dst[0] = make_float4(upd[0] * inv, upd[1] * inv, upd[2]  * inv, upd[3]  * inv);
            dst[1] = make_float4(upd[4] * inv, upd[5] * inv, upd[6]  * inv, upd[7]  * inv);
            dst[2] = make_float4(upd[8] * inv, upd[9] * inv, upd[10] * inv, upd[11] * inv);
        }
        __syncthreads();
    }
}

// ---------------------------------------------------------------------------
// Kernel B: mixed = w @ D, softmax over L (no max needed: |mixed| < 1).
// One warp per b, lane holds 4 l's. 128 threads, g_w prefetch.
// ---------------------------------------------------------------------------
__global__ __launch_bounds__(128, 7) void mix_softmax_kernel(
    const float* __restrict__ D,   // (B, NB, L)
    float* __restrict__ out)       // (E, B, L)
{
    const int warp = threadIdx.x >> 5;
    const int lane = threadIdx.x & 31;
    const size_t b = (size_t)blockIdx.x * 4 + warp;

    float4 Dreg[NB_];
    #pragma unroll
    for (int n = 0; n < NB_; n++)
        Dreg[n] = *reinterpret_cast<const float4*>(
            &D[(b * NB_ + n) * L_ + lane * 4]);

    const float* wp = &g_w[b * NB_];
    float wv_next = (lane < NB_) ? wp[lane] : 0.f;

    for (int e = 0; e < E_; e++) {
        float wv = wv_next;
        if (e + 1 < E_)
            wv_next = (lane < NB_) ? wp[(size_t)(e + 1) * B_ * NB_ + lane] : 0.f;

        float4 v = make_float4(0.f, 0.f, 0.f, 0.f);
        #pragma unroll
        for (int n = 0; n < NB_; n++) {
            float wn = __shfl_sync(0xffffffffu, wv, n);
            v.x = fmaf(wn, Dreg[n].x, v.x);
            v.y = fmaf(wn, Dreg[n].y, v.y);
            v.z = fmaf(wn, Dreg[n].z, v.z);
            v.w = fmaf(wn, Dreg[n].w, v.w);
        }

        float e0 = __expf(v.x), e1 = __expf(v.y);
        float e2 = __expf(v.z), e3 = __expf(v.w);
        float sm = (e0 + e1) + (e2 + e3);
        #pragma unroll
        for (int off = 16; off > 0; off >>= 1)
            sm += __shfl_xor_sync(0xffffffffu, sm, off);

        const float inv = 1.f / sm;
        *reinterpret_cast<float4*>(&out[((size_t)e * B_ + b) * L_ + lane * 4]) =
            make_float4(e0 * inv, e1 * inv, e2 * inv, e3 * inv);
    }
}

// ---------------------------------------------------------------------------
extern "C" void kernel_launch(void* const* d_in, const int* in_sizes, int n_in,
                              void* d_out, int out_size)
{
    const float* D  = (const float*)d_in[0];  // (B,NB,L)
    const float* X  = (const float*)d_in[1];  // (B,F)
    const float* bw = (const float*)d_in[2];  // (E,1,NB,1)
    const float* W1 = (const float*)d_in[3];  // (E,F,H)
    const float* b1 = (const float*)d_in[4];  // (E,H)
    const float* W2 = (const float*)d_in[5];  // (E,H,NB)
    const float* b2 = (const float*)d_in[6];  // (E,NB)
    float* out = (float*)d_out;               // (E,B,L)

    cudaFuncSetAttribute(mlp_tc_kernel,
                         cudaFuncAttributeMaxDynamicSharedMemorySize, SMEM_BYTES);
    dim3 gA(B_ / ROWS, NEG);
    mlp_tc_kernel<<<gA, 256, SMEM_BYTES>>>(X, bw, W1, b1, W2, b2);
    mix_softmax_kernel<<<B_ / 4, 128>>>(D, out);
}